// round 2
// baseline (speedup 1.0000x reference)
#include <cuda_runtime.h>
#include <cuda_fp16.h>
#include <cstdint>

// ---------------- problem dims ----------------
#define B_SZ 4
#define L_SZ 4096
#define D_SZ 2048
#define N_SZ 16
#define TOK  (B_SZ * L_SZ)      // 16384 tokens
#define ECOLS (3 * D_SZ)        // 6144 concatenated output cols (dt|b|c)

// ---------------- GEMM tiles ----------------
#define BM 256
#define BN 128
#define BK 32
#define PADK 40                 // halves per smem row (80 B, 16B-aligned, conflict-free)
#define A_BYTES (BM * PADK * 2) // 20480
#define B_BYTES (BN * PADK * 2) // 10240
#define STAGE_BYTES (A_BYTES + B_BYTES)   // 30720
#define SMEM_TOT (2 * STAGE_BYTES)        // 61440

// ---------------- scratch (device globals: allocation-free) ----------------
__device__ __half g_uh[(size_t)TOK * D_SZ];          // u fp16, [tok][k]
__device__ __half g_wh[(size_t)ECOLS * D_SZ];        // W^T fp16, [e][k]
__device__ float  g_uT [(size_t)B_SZ * D_SZ * L_SZ]; // (b,d,t)
__device__ float  g_dtT[(size_t)B_SZ * D_SZ * L_SZ];
__device__ float  g_bT [(size_t)B_SZ * D_SZ * L_SZ];
__device__ float  g_cT [(size_t)B_SZ * D_SZ * L_SZ];
__device__ float  g_yT [(size_t)B_SZ * D_SZ * L_SZ];

// ---------------- helpers ----------------
__device__ __forceinline__ uint32_t smem_u32(const void* p) {
    uint32_t a;
    asm("{ .reg .u64 t; cvta.to.shared.u64 t, %1; cvt.u32.u64 %0, t; }" : "=r"(a) : "l"(p));
    return a;
}
__device__ __forceinline__ void cp16(uint32_t dst, const void* src) {
    asm volatile("cp.async.cg.shared.global [%0], [%1], 16;" :: "r"(dst), "l"(src));
}
__device__ __forceinline__ void cp_commit() { asm volatile("cp.async.commit_group;"); }
__device__ __forceinline__ void cp_wait0()  { asm volatile("cp.async.wait_group 0;"); }

__device__ __forceinline__ void ldsm_x4(uint32_t& r0, uint32_t& r1, uint32_t& r2, uint32_t& r3,
                                        uint32_t addr) {
    asm volatile("ldmatrix.sync.aligned.m8n8.x4.shared.b16 {%0,%1,%2,%3}, [%4];"
                 : "=r"(r0), "=r"(r1), "=r"(r2), "=r"(r3) : "r"(addr));
}
__device__ __forceinline__ void mma16816(float* d, uint32_t a0, uint32_t a1, uint32_t a2,
                                         uint32_t a3, uint32_t b0, uint32_t b1) {
    asm volatile("mma.sync.aligned.m16n8k16.row.col.f32.f16.f16.f32 "
                 "{%0,%1,%2,%3}, {%4,%5,%6,%7}, {%8,%9}, {%0,%1,%2,%3};"
                 : "+f"(d[0]), "+f"(d[1]), "+f"(d[2]), "+f"(d[3])
                 : "r"(a0), "r"(a1), "r"(a2), "r"(a3), "r"(b0), "r"(b1));
}
__device__ __forceinline__ float softplusf(float x) {
    return fmaxf(x, 0.f) + log1pf(__expf(-fabsf(x)));
}

// ================= conversion / transpose kernels =================

__global__ void conv_u_kernel(const float* __restrict__ u) {
    __shared__ float tile[32][33];
    int dx  = blockIdx.x * 32 + threadIdx.x;
    int tok = blockIdx.y * 32 + threadIdx.y;
    float v = u[(size_t)tok * D_SZ + dx];
    g_uh[(size_t)tok * D_SZ + dx] = __float2half(v);
    tile[threadIdx.y][threadIdx.x] = v;
    __syncthreads();
    int dy   = blockIdx.x * 32 + threadIdx.y;
    int tok2 = blockIdx.y * 32 + threadIdx.x;
    int b = tok2 >> 12;
    g_uT[((size_t)b * D_SZ + dy) * L_SZ + (tok2 & (L_SZ - 1))] = tile[threadIdx.x][threadIdx.y];
}

__global__ void conv_w_kernel(const float* __restrict__ W, int ebase) {
    __shared__ float tile[32][33];
    int e = blockIdx.x * 32 + threadIdx.x;
    int k = blockIdx.y * 32 + threadIdx.y;
    tile[threadIdx.y][threadIdx.x] = W[(size_t)k * D_SZ + e];
    __syncthreads();
    int e2 = blockIdx.x * 32 + threadIdx.y;
    int k2 = blockIdx.y * 32 + threadIdx.x;
    g_wh[(size_t)(ebase + e2) * D_SZ + k2] = __float2half(tile[threadIdx.x][threadIdx.y]);
}

__global__ void transpose_y_kernel(float* __restrict__ y) {
    __shared__ float tile[32][33];
    int t  = blockIdx.x * 32 + threadIdx.x;
    int gg = blockIdx.y * 32 + threadIdx.y;
    tile[threadIdx.y][threadIdx.x] = g_yT[(size_t)gg * L_SZ + t];
    __syncthreads();
    int gg2 = blockIdx.y * 32 + threadIdx.x;
    int t2  = blockIdx.x * 32 + threadIdx.y;
    int b = gg2 >> 11;
    int d = gg2 & (D_SZ - 1);
    y[((size_t)b * L_SZ + t2) * D_SZ + d] = tile[threadIdx.x][threadIdx.y];
}

// ================= HMMA projection GEMM (sm_100-portable) =================
// C[t,e] = sum_k u16[t,k] * w16[e,k];  BM=256 x BN=128 x BK=32, 8 warps (4m x 2n),
// warp tile 64x64. Epilogue: +bias (+softplus for dt), transposed store to (b,e,t).

__global__ void __launch_bounds__(256, 1)
gemm_proj_kernel(const float* __restrict__ bdt, const float* __restrict__ bb,
                 const float* __restrict__ bc) {
    extern __shared__ char smem[];
    const uint32_t sb = smem_u32(smem);
    const int tid = threadIdx.x;
    const int wid = tid >> 5, lane = tid & 31;
    const int warpM = wid & 3, warpN = wid >> 2;

    const int mtile = blockIdx.x;               // 0..63
    const int ntile = blockIdx.y;               // 0..47
    const size_t arow0 = (size_t)mtile * BM;
    const size_t brow0 = (size_t)ntile * BN;

    float acc[4][8][4];
    #pragma unroll
    for (int i = 0; i < 4; ++i)
        #pragma unroll
        for (int j = 0; j < 8; ++j)
            #pragma unroll
            for (int k = 0; k < 4; ++k) acc[i][j][k] = 0.f;

    // cp.async index precompute: A = 1024 16B chunks (4/thread), B = 512 (2/thread)
    auto load_stage = [&](int kc, int stage) {
        const int k0 = kc * BK;
        const uint32_t abase = sb + stage * STAGE_BYTES;
        const uint32_t bbase = abase + A_BYTES;
        #pragma unroll
        for (int i = 0; i < 4; ++i) {
            int s = tid + i * 256;
            int r = s >> 2, c = s & 3;          // row 0..255, 16B chunk 0..3
            cp16(abase + r * (PADK * 2) + c * 16,
                 g_uh + (arow0 + r) * D_SZ + k0 + c * 8);
        }
        #pragma unroll
        for (int i = 0; i < 2; ++i) {
            int s = tid + i * 256;
            int r = s >> 2, c = s & 3;
            cp16(bbase + r * (PADK * 2) + c * 16,
                 g_wh + (brow0 + r) * D_SZ + k0 + c * 8);
        }
        cp_commit();
    };

    load_stage(0, 0);

    const int NITER = D_SZ / BK;                // 64
    for (int kc = 0; kc < NITER; ++kc) {
        cp_wait0();
        __syncthreads();
        if (kc + 1 < NITER) load_stage(kc + 1, (kc + 1) & 1);

        const uint32_t abase = sb + (kc & 1) * STAGE_BYTES;
        const uint32_t bbase = abase + A_BYTES;

        #pragma unroll
        for (int ks = 0; ks < 2; ++ks) {
            const int colb = ks * 32;           // 16 halves = 32 B
            uint32_t af[4][4], bf[4][4];
            #pragma unroll
            for (int mt = 0; mt < 4; ++mt) {
                int row = warpM * 64 + mt * 16 + (lane & 15);
                uint32_t addr = abase + row * (PADK * 2) + colb + ((lane >> 4) << 4);
                ldsm_x4(af[mt][0], af[mt][1], af[mt][2], af[mt][3], addr);
            }
            #pragma unroll
            for (int np = 0; np < 4; ++np) {
                int row = warpN * 64 + np * 16 + (lane & 7) + ((lane >> 4) << 3);
                uint32_t addr = bbase + row * (PADK * 2) + colb + (((lane >> 3) & 1) << 4);
                ldsm_x4(bf[np][0], bf[np][1], bf[np][2], bf[np][3], addr);
            }
            #pragma unroll
            for (int mt = 0; mt < 4; ++mt)
                #pragma unroll
                for (int np = 0; np < 4; ++np) {
                    mma16816(acc[mt][2 * np],     af[mt][0], af[mt][1], af[mt][2], af[mt][3],
                             bf[np][0], bf[np][1]);
                    mma16816(acc[mt][2 * np + 1], af[mt][0], af[mt][1], af[mt][2], af[mt][3],
                             bf[np][2], bf[np][3]);
                }
        }
        __syncthreads();
    }

    // ---------------- transposed epilogue via smem staging ----------------
    // Process 8 e-columns per chunk; sbuf layout [m 0..255][e 0..7] pad 9 floats.
    float* sbuf = (float*)smem;
    const int mat = ntile >> 4;                     // 0=dt 1=b 2=c
    const float* bias = (mat == 0) ? bdt : ((mat == 1) ? bb : bc);
    float* outp = (mat == 0) ? g_dtT : ((mat == 1) ? g_bT : g_cT);
    const int e_mat0 = (ntile & 15) * BN;
    const int tglob0 = mtile * BM;
    const int bidx = tglob0 >> 12;
    const int t0   = tglob0 & (L_SZ - 1);

    for (int ch = 0; ch < 16; ++ch) {
        __syncthreads();
        if (warpN == (ch >> 3)) {
            const int nt = ch & 7;
            #pragma unroll
            for (int mt = 0; mt < 4; ++mt) {
                int mbase = warpM * 64 + mt * 16 + (lane >> 2);
                int el = 2 * (lane & 3);
                sbuf[mbase * 9 + el]           = acc[mt][nt][0];
                sbuf[mbase * 9 + el + 1]       = acc[mt][nt][1];
                sbuf[(mbase + 8) * 9 + el]     = acc[mt][nt][2];
                sbuf[(mbase + 8) * 9 + el + 1] = acc[mt][nt][3];
            }
        }
        __syncthreads();
        #pragma unroll
        for (int r = 0; r < 8; ++r) {
            int e = e_mat0 + ch * 8 + r;
            float v = sbuf[tid * 9 + r] + bias[e];
            if (mat == 0) v = softplusf(v) + 1e-4f;
            outp[((size_t)bidx * D_SZ + e) * L_SZ + t0 + tid] = v;
        }
    }
}

// ================= selective scan =================
// 16 lanes per (b,d); lane n holds z[n] = C_base[d,n] * x[n].
// z' = exp2(dt*A*log2e)*z + (dt*b*u)*(B_base*C_base);  y = c * sum_n(z) + D*u.

__global__ void __launch_bounds__(256) scan_kernel(const float* __restrict__ a_raw,
                                                   const float* __restrict__ Bb_,
                                                   const float* __restrict__ Cb_,
                                                   const float* __restrict__ Dp,
                                                   float* __restrict__ carry) {
    const unsigned FULL = 0xffffffffu;
    int tid = threadIdx.x;
    int g = blockIdx.x * 16 + (tid >> 4);   // (b,d) pair, 8192 total
    int ln = tid & 15;
    int d = g & (D_SZ - 1);
    size_t base = (size_t)g * L_SZ;

    float ar = a_raw[d * N_SZ + ln];
    float A2 = -softplusf(ar) * 1.4426950408889634f;   // A * log2(e)
    float Cb = Cb_[d * N_SZ + ln];
    float BC = Bb_[d * N_SZ + ln] * Cb;
    float Dv = Dp[d];
    float z = 0.f;

    float u_l  = g_uT[base + ln];
    float dt_l = g_dtT[base + ln];
    float b_l  = g_bT[base + ln];
    float c_l  = g_cT[base + ln];
    float gl = dt_l * b_l * u_l;
    float du = Dv * u_l;

    for (int t0 = 0; t0 < L_SZ; t0 += 16) {
        float dt2 = 0.f, g2 = 0.f, c2 = 0.f, du2 = 0.f;
        if (t0 + 16 < L_SZ) {
            size_t o = base + t0 + 16 + ln;
            float un = g_uT[o], dtn = g_dtT[o], bn = g_bT[o], cn = g_cT[o];
            g2 = dtn * bn * un; du2 = Dv * un; dt2 = dtn; c2 = cn;
        }
        float yk = 0.f;
        #pragma unroll
        for (int j = 0; j < 16; ++j) {
            float dts = __shfl_sync(FULL, dt_l, j, 16);
            float gs  = __shfl_sync(FULL, gl,  j, 16);
            float ab;
            asm("ex2.approx.f32 %0, %1;" : "=f"(ab) : "f"(dts * A2));
            z = fmaf(ab, z, gs * BC);
            float s = z;
            s += __shfl_xor_sync(FULL, s, 1, 16);
            s += __shfl_xor_sync(FULL, s, 2, 16);
            s += __shfl_xor_sync(FULL, s, 4, 16);
            s += __shfl_xor_sync(FULL, s, 8, 16);
            float yv = fmaf(c_l, s, du);
            if (ln == j) yk = yv;
        }
        g_yT[base + t0 + ln] = yk;
        dt_l = dt2; gl = g2; c_l = c2; du = du2;
    }
    float x = (Cb != 0.f) ? (z / Cb) : 0.f;
    carry[(size_t)g * N_SZ + ln] = x;
}

// ================= launch =================
extern "C" void kernel_launch(void* const* d_in, const int* in_sizes, int n_in,
                              void* d_out, int out_size) {
    const float* u     = (const float*)d_in[0];
    const float* Wdt   = (const float*)d_in[1];
    const float* bdt   = (const float*)d_in[2];
    const float* Wb    = (const float*)d_in[3];
    const float* bb    = (const float*)d_in[4];
    const float* Wc    = (const float*)d_in[5];
    const float* bc    = (const float*)d_in[6];
    const float* a_raw = (const float*)d_in[7];
    const float* Bbase = (const float*)d_in[8];
    const float* Cbase = (const float*)d_in[9];
    const float* Dp    = (const float*)d_in[10];

    float* out   = (float*)d_out;
    float* carry = out;                                  // (B, d, N) first
    float* y     = out + (size_t)B_SZ * D_SZ * N_SZ;     // then (B, L, d)

    cudaFuncSetAttribute(gemm_proj_kernel, cudaFuncAttributeMaxDynamicSharedMemorySize,
                         SMEM_TOT);

    conv_u_kernel<<<dim3(D_SZ / 32, TOK / 32), dim3(32, 32)>>>(u);
    conv_w_kernel<<<dim3(D_SZ / 32, D_SZ / 32), dim3(32, 32)>>>(Wdt, 0);
    conv_w_kernel<<<dim3(D_SZ / 32, D_SZ / 32), dim3(32, 32)>>>(Wb, D_SZ);
    conv_w_kernel<<<dim3(D_SZ / 32, D_SZ / 32), dim3(32, 32)>>>(Wc, 2 * D_SZ);
    gemm_proj_kernel<<<dim3(TOK / BM, ECOLS / BN), 256, SMEM_TOT>>>(bdt, bb, bc);
    scan_kernel<<<(B_SZ * D_SZ) / 16, 256>>>(a_raw, Bbase, Cbase, Dp, carry);
    transpose_y_kernel<<<dim3(L_SZ / 32, (B_SZ * D_SZ) / 32), dim3(32, 32)>>>(y);
}

// round 4
// speedup vs baseline: 3.2313x; 3.2313x over previous
#include <cuda_runtime.h>
#include <cuda_fp16.h>
#include <cstdint>

// ---------------- problem dims ----------------
#define B_SZ 4
#define L_SZ 4096
#define D_SZ 2048
#define N_SZ 16
#define TOK  (B_SZ * L_SZ)      // 16384 tokens
#define ECOLS (3 * D_SZ)        // 6144 concatenated output cols (dt|b|c)

// ---------------- GEMM tiles ----------------
#define BM 256
#define BN 128
#define BK 32
#define PADK 40                 // halves per smem row (80 B, 16B-aligned, conflict-free)
#define A_BYTES (BM * PADK * 2) // 20480
#define B_BYTES (BN * PADK * 2) // 10240
#define STAGE_BYTES (A_BYTES + B_BYTES)   // 30720
#define SMEM_TOT (2 * STAGE_BYTES)        // 61440

// ---------------- scratch (device globals: allocation-free) ----------------
__device__ __half g_uh[(size_t)TOK * D_SZ];          // u fp16, [tok][k]
__device__ __half g_wh[(size_t)ECOLS * D_SZ];        // W^T fp16, [e][k]
__device__ float  g_uT [(size_t)B_SZ * D_SZ * L_SZ]; // (b,d,t)
__device__ float  g_dtT[(size_t)B_SZ * D_SZ * L_SZ];
__device__ float  g_bT [(size_t)B_SZ * D_SZ * L_SZ];
__device__ float  g_cT [(size_t)B_SZ * D_SZ * L_SZ];
__device__ float  g_yT [(size_t)B_SZ * D_SZ * L_SZ];

// ---------------- helpers ----------------
__device__ __forceinline__ uint32_t smem_u32(const void* p) {
    uint32_t a;
    asm("{ .reg .u64 t; cvta.to.shared.u64 t, %1; cvt.u32.u64 %0, t; }" : "=r"(a) : "l"(p));
    return a;
}
__device__ __forceinline__ void cp16(uint32_t dst, const void* src) {
    asm volatile("cp.async.cg.shared.global [%0], [%1], 16;" :: "r"(dst), "l"(src));
}
__device__ __forceinline__ void cp_commit() { asm volatile("cp.async.commit_group;"); }
__device__ __forceinline__ void cp_wait1()  { asm volatile("cp.async.wait_group 1;"); }
__device__ __forceinline__ void cp_wait0()  { asm volatile("cp.async.wait_group 0;"); }

__device__ __forceinline__ void ldsm_x4(uint32_t& r0, uint32_t& r1, uint32_t& r2, uint32_t& r3,
                                        uint32_t addr) {
    asm volatile("ldmatrix.sync.aligned.m8n8.x4.shared.b16 {%0,%1,%2,%3}, [%4];"
                 : "=r"(r0), "=r"(r1), "=r"(r2), "=r"(r3) : "r"(addr));
}
__device__ __forceinline__ void mma16816(float* d, uint32_t a0, uint32_t a1, uint32_t a2,
                                         uint32_t a3, uint32_t b0, uint32_t b1) {
    asm volatile("mma.sync.aligned.m16n8k16.row.col.f32.f16.f16.f32 "
                 "{%0,%1,%2,%3}, {%4,%5,%6,%7}, {%8,%9}, {%0,%1,%2,%3};"
                 : "+f"(d[0]), "+f"(d[1]), "+f"(d[2]), "+f"(d[3])
                 : "r"(a0), "r"(a1), "r"(a2), "r"(a3), "r"(b0), "r"(b1));
}
__device__ __forceinline__ float softplusf(float x) {
    return fmaxf(x, 0.f) + log1pf(__expf(-fabsf(x)));
}

// ================= conversion / transpose kernels =================

__global__ void conv_u_kernel(const float* __restrict__ u) {
    __shared__ float tile[32][33];
    int dx  = blockIdx.x * 32 + threadIdx.x;
    int tok = blockIdx.y * 32 + threadIdx.y;
    float v = u[(size_t)tok * D_SZ + dx];
    g_uh[(size_t)tok * D_SZ + dx] = __float2half(v);
    tile[threadIdx.y][threadIdx.x] = v;
    __syncthreads();
    int dy   = blockIdx.x * 32 + threadIdx.y;
    int tok2 = blockIdx.y * 32 + threadIdx.x;
    int b = tok2 >> 12;
    g_uT[((size_t)b * D_SZ + dy) * L_SZ + (tok2 & (L_SZ - 1))] = tile[threadIdx.x][threadIdx.y];
}

__global__ void conv_w_kernel(const float* __restrict__ W, int ebase) {
    __shared__ float tile[32][33];
    int e = blockIdx.x * 32 + threadIdx.x;
    int k = blockIdx.y * 32 + threadIdx.y;
    tile[threadIdx.y][threadIdx.x] = W[(size_t)k * D_SZ + e];
    __syncthreads();
    int e2 = blockIdx.x * 32 + threadIdx.y;
    int k2 = blockIdx.y * 32 + threadIdx.x;
    g_wh[(size_t)(ebase + e2) * D_SZ + k2] = __float2half(tile[threadIdx.x][threadIdx.y]);
}

__global__ void transpose_y_kernel(float* __restrict__ y) {
    __shared__ float tile[32][33];
    int t  = blockIdx.x * 32 + threadIdx.x;
    int gg = blockIdx.y * 32 + threadIdx.y;
    tile[threadIdx.y][threadIdx.x] = g_yT[(size_t)gg * L_SZ + t];
    __syncthreads();
    int gg2 = blockIdx.y * 32 + threadIdx.x;
    int t2  = blockIdx.x * 32 + threadIdx.y;
    int b = gg2 >> 11;
    int d = gg2 & (D_SZ - 1);
    y[((size_t)b * L_SZ + t2) * D_SZ + d] = tile[threadIdx.x][threadIdx.y];
}

// ================= HMMA projection GEMM (sm_100-portable) =================
// C[t,e] = sum_k u16[t,k] * w16[e,k];  BM=256 x BN=128 x BK=32, 8 warps (4m x 2n),
// warp tile 64x64. Epilogue: +bias (+softplus for dt), transposed store to (b,e,t).

__global__ void __launch_bounds__(256, 1)
gemm_proj_kernel(const float* __restrict__ bdt, const float* __restrict__ bb,
                 const float* __restrict__ bc) {
    extern __shared__ char smem[];
    const uint32_t sb = smem_u32(smem);
    const int tid = threadIdx.x;
    const int wid = tid >> 5, lane = tid & 31;
    const int warpM = wid & 3, warpN = wid >> 2;

    const int mtile = blockIdx.x;               // 0..63
    const int ntile = blockIdx.y;               // 0..47
    const size_t arow0 = (size_t)mtile * BM;
    const size_t brow0 = (size_t)ntile * BN;

    float acc[4][8][4];
    #pragma unroll
    for (int i = 0; i < 4; ++i)
        #pragma unroll
        for (int j = 0; j < 8; ++j)
            #pragma unroll
            for (int k = 0; k < 4; ++k) acc[i][j][k] = 0.f;

    auto load_stage = [&](int kc, int stage) {
        const int k0 = kc * BK;
        const uint32_t abase = sb + stage * STAGE_BYTES;
        const uint32_t bbase = abase + A_BYTES;
        #pragma unroll
        for (int i = 0; i < 4; ++i) {
            int s = tid + i * 256;
            int r = s >> 2, c = s & 3;          // row 0..255, 16B chunk 0..3
            cp16(abase + r * (PADK * 2) + c * 16,
                 g_uh + (arow0 + r) * D_SZ + k0 + c * 8);
        }
        #pragma unroll
        for (int i = 0; i < 2; ++i) {
            int s = tid + i * 256;
            int r = s >> 2, c = s & 3;
            cp16(bbase + r * (PADK * 2) + c * 16,
                 g_wh + (brow0 + r) * D_SZ + k0 + c * 8);
        }
        cp_commit();
    };

    load_stage(0, 0);

    const int NITER = D_SZ / BK;                // 64
    for (int kc = 0; kc < NITER; ++kc) {
        // issue next stage first, then wait for current (leaves next in flight)
        if (kc + 1 < NITER) {
            load_stage(kc + 1, (kc + 1) & 1);
            cp_wait1();
        } else {
            cp_wait0();
        }
        __syncthreads();

        const uint32_t abase = sb + (kc & 1) * STAGE_BYTES;
        const uint32_t bbase = abase + A_BYTES;

        #pragma unroll
        for (int ks = 0; ks < 2; ++ks) {
            const int colb = ks * 32;           // 16 halves = 32 B
            uint32_t af[4][4], bf[4][4];
            #pragma unroll
            for (int mt = 0; mt < 4; ++mt) {
                int row = warpM * 64 + mt * 16 + (lane & 15);
                uint32_t addr = abase + row * (PADK * 2) + colb + ((lane >> 4) << 4);
                ldsm_x4(af[mt][0], af[mt][1], af[mt][2], af[mt][3], addr);
            }
            #pragma unroll
            for (int np = 0; np < 4; ++np) {
                int row = warpN * 64 + np * 16 + (lane & 7) + ((lane >> 4) << 3);
                uint32_t addr = bbase + row * (PADK * 2) + colb + (((lane >> 3) & 1) << 4);
                ldsm_x4(bf[np][0], bf[np][1], bf[np][2], bf[np][3], addr);
            }
            #pragma unroll
            for (int mt = 0; mt < 4; ++mt)
                #pragma unroll
                for (int np = 0; np < 4; ++np) {
                    mma16816(acc[mt][2 * np],     af[mt][0], af[mt][1], af[mt][2], af[mt][3],
                             bf[np][0], bf[np][1]);
                    mma16816(acc[mt][2 * np + 1], af[mt][0], af[mt][1], af[mt][2], af[mt][3],
                             bf[np][2], bf[np][3]);
                }
        }
        __syncthreads();
    }

    // ---------------- transposed epilogue via smem staging ----------------
    // Process 8 e-columns per chunk; sbuf layout [m 0..255][e 0..7] pad 9 floats.
    // FULLY UNROLLED: ch must be compile-time so acc[][] keeps static indices
    // (dynamic indexing demotes the whole accumulator array to local memory).
    float* sbuf = (float*)smem;
    const int mat = ntile >> 4;                     // 0=dt 1=b 2=c
    const float* bias = (mat == 0) ? bdt : ((mat == 1) ? bb : bc);
    float* outp = (mat == 0) ? g_dtT : ((mat == 1) ? g_bT : g_cT);
    const int e_mat0 = (ntile & 15) * BN;
    const int tglob0 = mtile * BM;
    const int bidx = tglob0 >> 12;
    const int t0   = tglob0 & (L_SZ - 1);

    #pragma unroll
    for (int ch = 0; ch < 16; ++ch) {
        __syncthreads();
        if (warpN == (ch >> 3)) {
            const int nt = ch & 7;                  // compile-time after unroll
            #pragma unroll
            for (int mt = 0; mt < 4; ++mt) {
                int mbase = warpM * 64 + mt * 16 + (lane >> 2);
                int el = 2 * (lane & 3);
                sbuf[mbase * 9 + el]           = acc[mt][nt][0];
                sbuf[mbase * 9 + el + 1]       = acc[mt][nt][1];
                sbuf[(mbase + 8) * 9 + el]     = acc[mt][nt][2];
                sbuf[(mbase + 8) * 9 + el + 1] = acc[mt][nt][3];
            }
        }
        __syncthreads();
        #pragma unroll
        for (int r = 0; r < 8; ++r) {
            int e = e_mat0 + ch * 8 + r;
            float v = sbuf[tid * 9 + r] + bias[e];
            if (mat == 0) v = softplusf(v) + 1e-4f;
            outp[((size_t)bidx * D_SZ + e) * L_SZ + t0 + tid] = v;
        }
    }
}

// ================= selective scan =================
// 16 lanes per (b,d); lane n holds z[n] = C_base[d,n] * x[n].
// z' = exp2(dt*A*log2e)*z + (dt*b*u)*(B_base*C_base);  y = c * sum_n(z) + D*u.

__global__ void __launch_bounds__(256) scan_kernel(const float* __restrict__ a_raw,
                                                   const float* __restrict__ Bb_,
                                                   const float* __restrict__ Cb_,
                                                   const float* __restrict__ Dp,
                                                   float* __restrict__ carry) {
    const unsigned FULL = 0xffffffffu;
    int tid = threadIdx.x;
    int g = blockIdx.x * 16 + (tid >> 4);   // (b,d) pair, 8192 total
    int ln = tid & 15;
    int d = g & (D_SZ - 1);
    size_t base = (size_t)g * L_SZ;

    float ar = a_raw[d * N_SZ + ln];
    float A2 = -softplusf(ar) * 1.4426950408889634f;   // A * log2(e)
    float Cb = Cb_[d * N_SZ + ln];
    float BC = Bb_[d * N_SZ + ln] * Cb;
    float Dv = Dp[d];
    float z = 0.f;

    float u_l  = g_uT[base + ln];
    float dt_l = g_dtT[base + ln];
    float b_l  = g_bT[base + ln];
    float c_l  = g_cT[base + ln];
    float gl = dt_l * b_l * u_l;
    float du = Dv * u_l;

    for (int t0 = 0; t0 < L_SZ; t0 += 16) {
        float dt2 = 0.f, g2 = 0.f, c2 = 0.f, du2 = 0.f;
        if (t0 + 16 < L_SZ) {
            size_t o = base + t0 + 16 + ln;
            float un = g_uT[o], dtn = g_dtT[o], bn = g_bT[o], cn = g_cT[o];
            g2 = dtn * bn * un; du2 = Dv * un; dt2 = dtn; c2 = cn;
        }
        float yk = 0.f;
        #pragma unroll
        for (int j = 0; j < 16; ++j) {
            float dts = __shfl_sync(FULL, dt_l, j, 16);
            float gs  = __shfl_sync(FULL, gl,  j, 16);
            float ab;
            asm("ex2.approx.f32 %0, %1;" : "=f"(ab) : "f"(dts * A2));
            z = fmaf(ab, z, gs * BC);
            float s = z;
            s += __shfl_xor_sync(FULL, s, 1, 16);
            s += __shfl_xor_sync(FULL, s, 2, 16);
            s += __shfl_xor_sync(FULL, s, 4, 16);
            s += __shfl_xor_sync(FULL, s, 8, 16);
            float yv = fmaf(c_l, s, du);
            if (ln == j) yk = yv;
        }
        g_yT[base + t0 + ln] = yk;
        dt_l = dt2; gl = g2; c_l = c2; du = du2;
    }
    float x = (Cb != 0.f) ? (z / Cb) : 0.f;
    carry[(size_t)g * N_SZ + ln] = x;
}

// ================= launch =================
extern "C" void kernel_launch(void* const* d_in, const int* in_sizes, int n_in,
                              void* d_out, int out_size) {
    const float* u     = (const float*)d_in[0];
    const float* Wdt   = (const float*)d_in[1];
    const float* bdt   = (const float*)d_in[2];
    const float* Wb    = (const float*)d_in[3];
    const float* bb    = (const float*)d_in[4];
    const float* Wc    = (const float*)d_in[5];
    const float* bc    = (const float*)d_in[6];
    const float* a_raw = (const float*)d_in[7];
    const float* Bbase = (const float*)d_in[8];
    const float* Cbase = (const float*)d_in[9];
    const float* Dp    = (const float*)d_in[10];

    float* out   = (float*)d_out;
    float* carry = out;                                  // (B, d, N) first
    float* y     = out + (size_t)B_SZ * D_SZ * N_SZ;     // then (B, L, d)

    cudaFuncSetAttribute(gemm_proj_kernel, cudaFuncAttributeMaxDynamicSharedMemorySize,
                         SMEM_TOT);

    conv_u_kernel<<<dim3(D_SZ / 32, TOK / 32), dim3(32, 32)>>>(u);
    conv_w_kernel<<<dim3(D_SZ / 32, D_SZ / 32), dim3(32, 32)>>>(Wdt, 0);
    conv_w_kernel<<<dim3(D_SZ / 32, D_SZ / 32), dim3(32, 32)>>>(Wb, D_SZ);
    conv_w_kernel<<<dim3(D_SZ / 32, D_SZ / 32), dim3(32, 32)>>>(Wc, 2 * D_SZ);
    gemm_proj_kernel<<<dim3(TOK / BM, ECOLS / BN), 256, SMEM_TOT>>>(bdt, bb, bc);
    scan_kernel<<<(B_SZ * D_SZ) / 16, 256>>>(a_raw, Bbase, Cbase, Dp, carry);
    transpose_y_kernel<<<dim3(L_SZ / 32, (B_SZ * D_SZ) / 32), dim3(32, 32)>>>(y);
}

// round 5
// speedup vs baseline: 3.2619x; 1.0095x over previous
#include <cuda_runtime.h>
#include <cuda_fp16.h>
#include <cstdint>

// ---------------- problem dims ----------------
#define B_SZ 4
#define L_SZ 4096
#define D_SZ 2048
#define N_SZ 16
#define TOK  (B_SZ * L_SZ)      // 16384 tokens
#define ECOLS (3 * D_SZ)        // 6144 concatenated output cols (dt|b|c)

// ---------------- GEMM tiles ----------------
#define BM 256
#define BN 128
#define BK 32
#define PADK 40                 // halves per smem row (80 B, 16B-aligned, conflict-free)
#define A_BYTES (BM * PADK * 2) // 20480
#define B_BYTES (BN * PADK * 2) // 10240
#define STAGE_BYTES (A_BYTES + B_BYTES)   // 30720
#define NSTAGE 4
#define SMEM_TOT (NSTAGE * STAGE_BYTES)   // 122880

// ---------------- scratch (device globals: allocation-free) ----------------
__device__ __half g_uh[(size_t)TOK * D_SZ];          // u fp16, [tok][k]
__device__ __half g_wh[(size_t)ECOLS * D_SZ];        // W^T fp16, [e][k]
__device__ float  g_uT [(size_t)B_SZ * D_SZ * L_SZ]; // (b,d,t)
__device__ float  g_dtT[(size_t)B_SZ * D_SZ * L_SZ];
__device__ float  g_bT [(size_t)B_SZ * D_SZ * L_SZ];
__device__ float  g_cT [(size_t)B_SZ * D_SZ * L_SZ];
__device__ float  g_yT [(size_t)B_SZ * D_SZ * L_SZ];

// ---------------- helpers ----------------
__device__ __forceinline__ uint32_t smem_u32(const void* p) {
    uint32_t a;
    asm("{ .reg .u64 t; cvta.to.shared.u64 t, %1; cvt.u32.u64 %0, t; }" : "=r"(a) : "l"(p));
    return a;
}
__device__ __forceinline__ void cp16(uint32_t dst, const void* src) {
    asm volatile("cp.async.cg.shared.global [%0], [%1], 16;" :: "r"(dst), "l"(src));
}
__device__ __forceinline__ void cp_commit() { asm volatile("cp.async.commit_group;"); }
__device__ __forceinline__ void cp_wait2()  { asm volatile("cp.async.wait_group 2;"); }

__device__ __forceinline__ void ldsm_x4(uint32_t& r0, uint32_t& r1, uint32_t& r2, uint32_t& r3,
                                        uint32_t addr) {
    asm volatile("ldmatrix.sync.aligned.m8n8.x4.shared.b16 {%0,%1,%2,%3}, [%4];"
                 : "=r"(r0), "=r"(r1), "=r"(r2), "=r"(r3) : "r"(addr));
}
__device__ __forceinline__ void mma16816(float* d, uint32_t a0, uint32_t a1, uint32_t a2,
                                         uint32_t a3, uint32_t b0, uint32_t b1) {
    asm volatile("mma.sync.aligned.m16n8k16.row.col.f32.f16.f16.f32 "
                 "{%0,%1,%2,%3}, {%4,%5,%6,%7}, {%8,%9}, {%0,%1,%2,%3};"
                 : "+f"(d[0]), "+f"(d[1]), "+f"(d[2]), "+f"(d[3])
                 : "r"(a0), "r"(a1), "r"(a2), "r"(a3), "r"(b0), "r"(b1));
}
__device__ __forceinline__ float softplusf(float x) {
    return fmaxf(x, 0.f) + log1pf(__expf(-fabsf(x)));
}

// ================= conversion / transpose kernels =================

__global__ void conv_u_kernel(const float* __restrict__ u) {
    __shared__ float tile[32][33];
    int dx  = blockIdx.x * 32 + threadIdx.x;
    int tok = blockIdx.y * 32 + threadIdx.y;
    float v = u[(size_t)tok * D_SZ + dx];
    g_uh[(size_t)tok * D_SZ + dx] = __float2half(v);
    tile[threadIdx.y][threadIdx.x] = v;
    __syncthreads();
    int dy   = blockIdx.x * 32 + threadIdx.y;
    int tok2 = blockIdx.y * 32 + threadIdx.x;
    int b = tok2 >> 12;
    g_uT[((size_t)b * D_SZ + dy) * L_SZ + (tok2 & (L_SZ - 1))] = tile[threadIdx.x][threadIdx.y];
}

__global__ void conv_w_kernel(const float* __restrict__ W, int ebase) {
    __shared__ float tile[32][33];
    int e = blockIdx.x * 32 + threadIdx.x;
    int k = blockIdx.y * 32 + threadIdx.y;
    tile[threadIdx.y][threadIdx.x] = W[(size_t)k * D_SZ + e];
    __syncthreads();
    int e2 = blockIdx.x * 32 + threadIdx.y;
    int k2 = blockIdx.y * 32 + threadIdx.x;
    g_wh[(size_t)(ebase + e2) * D_SZ + k2] = __float2half(tile[threadIdx.x][threadIdx.y]);
}

__global__ void transpose_y_kernel(float* __restrict__ y) {
    __shared__ float tile[32][33];
    int t  = blockIdx.x * 32 + threadIdx.x;
    int gg = blockIdx.y * 32 + threadIdx.y;
    tile[threadIdx.y][threadIdx.x] = g_yT[(size_t)gg * L_SZ + t];
    __syncthreads();
    int gg2 = blockIdx.y * 32 + threadIdx.x;
    int t2  = blockIdx.x * 32 + threadIdx.y;
    int b = gg2 >> 11;
    int d = gg2 & (D_SZ - 1);
    y[((size_t)b * L_SZ + t2) * D_SZ + d] = tile[threadIdx.x][threadIdx.y];
}

// ================= HMMA projection GEMM (sm_100-portable) =================
// C[t,e] = sum_k u16[t,k] * w16[e,k];  BM=256 x BN=128 x BK=32, 8 warps (4m x 2n),
// warp tile 64x64, 4-stage cp.async pipeline, ONE barrier per K-iteration.

__global__ void __launch_bounds__(256, 1)
gemm_proj_kernel(const float* __restrict__ bdt, const float* __restrict__ bb,
                 const float* __restrict__ bc) {
    extern __shared__ char smem[];
    const uint32_t sb = smem_u32(smem);
    const int tid = threadIdx.x;
    const int wid = tid >> 5, lane = tid & 31;
    const int warpM = wid & 3, warpN = wid >> 2;

    const int mtile = blockIdx.x;               // 0..63
    const int ntile = blockIdx.y;               // 0..47
    const size_t arow0 = (size_t)mtile * BM;
    const size_t brow0 = (size_t)ntile * BN;

    float acc[4][8][4];
    #pragma unroll
    for (int i = 0; i < 4; ++i)
        #pragma unroll
        for (int j = 0; j < 8; ++j)
            #pragma unroll
            for (int k = 0; k < 4; ++k) acc[i][j][k] = 0.f;

    auto load_stage = [&](int kc, int stage) {
        const int k0 = kc * BK;
        const uint32_t abase = sb + stage * STAGE_BYTES;
        const uint32_t bbase = abase + A_BYTES;
        #pragma unroll
        for (int i = 0; i < 4; ++i) {
            int s = tid + i * 256;
            int r = s >> 2, c = s & 3;          // row 0..255, 16B chunk 0..3
            cp16(abase + r * (PADK * 2) + c * 16,
                 g_uh + (arow0 + r) * D_SZ + k0 + c * 8);
        }
        #pragma unroll
        for (int i = 0; i < 2; ++i) {
            int s = tid + i * 256;
            int r = s >> 2, c = s & 3;
            cp16(bbase + r * (PADK * 2) + c * 16,
                 g_wh + (brow0 + r) * D_SZ + k0 + c * 8);
        }
        cp_commit();
    };

    // prologue: stages 0..2 in flight
    load_stage(0, 0);
    load_stage(1, 1);
    load_stage(2, 2);

    const int NITER = D_SZ / BK;                // 64
    for (int kc = 0; kc < NITER; ++kc) {
        // committed groups so far = kc + 3; <=2 outstanding => stage kc complete
        cp_wait2();
        __syncthreads();   // everyone's stage-kc data visible; all readers of
                           // buffer (kc-1)%4 have passed (they finished compute
                           // of kc-1 before reaching this barrier)
        if (kc + 3 < NITER) load_stage(kc + 3, (kc + 3) & 3);
        else                cp_commit();        // keep group-count semantics exact

        const uint32_t abase = sb + (kc & 3) * STAGE_BYTES;
        const uint32_t bbase = abase + A_BYTES;

        #pragma unroll
        for (int ks = 0; ks < 2; ++ks) {
            const int colb = ks * 32;           // 16 halves = 32 B
            uint32_t af[4][4], bf[4][4];
            #pragma unroll
            for (int mt = 0; mt < 4; ++mt) {
                int row = warpM * 64 + mt * 16 + (lane & 15);
                uint32_t addr = abase + row * (PADK * 2) + colb + ((lane >> 4) << 4);
                ldsm_x4(af[mt][0], af[mt][1], af[mt][2], af[mt][3], addr);
            }
            #pragma unroll
            for (int np = 0; np < 4; ++np) {
                int row = warpN * 64 + np * 16 + (lane & 7) + ((lane >> 4) << 3);
                uint32_t addr = bbase + row * (PADK * 2) + colb + (((lane >> 3) & 1) << 4);
                ldsm_x4(bf[np][0], bf[np][1], bf[np][2], bf[np][3], addr);
            }
            #pragma unroll
            for (int mt = 0; mt < 4; ++mt)
                #pragma unroll
                for (int np = 0; np < 4; ++np) {
                    mma16816(acc[mt][2 * np],     af[mt][0], af[mt][1], af[mt][2], af[mt][3],
                             bf[np][0], bf[np][1]);
                    mma16816(acc[mt][2 * np + 1], af[mt][0], af[mt][1], af[mt][2], af[mt][3],
                             bf[np][2], bf[np][3]);
                }
        }
    }
    __syncthreads();   // mainloop done before epilogue reuses smem

    // ---------------- transposed epilogue via smem staging ----------------
    // FULLY UNROLLED so acc[][] keeps static indices (stays in registers).
    float* sbuf = (float*)smem;
    const int mat = ntile >> 4;                     // 0=dt 1=b 2=c
    const float* bias = (mat == 0) ? bdt : ((mat == 1) ? bb : bc);
    float* outp = (mat == 0) ? g_dtT : ((mat == 1) ? g_bT : g_cT);
    const int e_mat0 = (ntile & 15) * BN;
    const int tglob0 = mtile * BM;
    const int bidx = tglob0 >> 12;
    const int t0   = tglob0 & (L_SZ - 1);

    #pragma unroll
    for (int ch = 0; ch < 16; ++ch) {
        __syncthreads();
        if (warpN == (ch >> 3)) {
            const int nt = ch & 7;                  // compile-time after unroll
            #pragma unroll
            for (int mt = 0; mt < 4; ++mt) {
                int mbase = warpM * 64 + mt * 16 + (lane >> 2);
                int el = 2 * (lane & 3);
                sbuf[mbase * 9 + el]           = acc[mt][nt][0];
                sbuf[mbase * 9 + el + 1]       = acc[mt][nt][1];
                sbuf[(mbase + 8) * 9 + el]     = acc[mt][nt][2];
                sbuf[(mbase + 8) * 9 + el + 1] = acc[mt][nt][3];
            }
        }
        __syncthreads();
        #pragma unroll
        for (int r = 0; r < 8; ++r) {
            int e = e_mat0 + ch * 8 + r;
            float v = sbuf[tid * 9 + r] + bias[e];
            if (mat == 0) v = softplusf(v) + 1e-4f;
            outp[((size_t)bidx * D_SZ + e) * L_SZ + t0 + tid] = v;
        }
    }
}

// ================= selective scan =================
// 16 lanes per (b,d); lane n holds z[n] = C_base[d,n] * x[n].
// z' = exp2(dt*A*log2e)*z + (dt*b*u)*(B_base*C_base);  y = c * sum_n(z) + D*u.

__global__ void __launch_bounds__(256) scan_kernel(const float* __restrict__ a_raw,
                                                   const float* __restrict__ Bb_,
                                                   const float* __restrict__ Cb_,
                                                   const float* __restrict__ Dp,
                                                   float* __restrict__ carry) {
    const unsigned FULL = 0xffffffffu;
    int tid = threadIdx.x;
    int g = blockIdx.x * 16 + (tid >> 4);   // (b,d) pair, 8192 total
    int ln = tid & 15;
    int d = g & (D_SZ - 1);
    size_t base = (size_t)g * L_SZ;

    float ar = a_raw[d * N_SZ + ln];
    float A2 = -softplusf(ar) * 1.4426950408889634f;   // A * log2(e)
    float Cb = Cb_[d * N_SZ + ln];
    float BC = Bb_[d * N_SZ + ln] * Cb;
    float Dv = Dp[d];
    float z = 0.f;

    float u_l  = g_uT[base + ln];
    float dt_l = g_dtT[base + ln];
    float b_l  = g_bT[base + ln];
    float c_l  = g_cT[base + ln];
    float gl = dt_l * b_l * u_l;
    float du = Dv * u_l;

    for (int t0 = 0; t0 < L_SZ; t0 += 16) {
        float dt2 = 0.f, g2 = 0.f, c2 = 0.f, du2 = 0.f;
        if (t0 + 16 < L_SZ) {
            size_t o = base + t0 + 16 + ln;
            float un = g_uT[o], dtn = g_dtT[o], bn = g_bT[o], cn = g_cT[o];
            g2 = dtn * bn * un; du2 = Dv * un; dt2 = dtn; c2 = cn;
        }
        float yk = 0.f;
        #pragma unroll
        for (int j = 0; j < 16; ++j) {
            float dts = __shfl_sync(FULL, dt_l, j, 16);
            float gs  = __shfl_sync(FULL, gl,  j, 16);
            float ab;
            asm("ex2.approx.f32 %0, %1;" : "=f"(ab) : "f"(dts * A2));
            z = fmaf(ab, z, gs * BC);
            float s = z;
            s += __shfl_xor_sync(FULL, s, 1, 16);
            s += __shfl_xor_sync(FULL, s, 2, 16);
            s += __shfl_xor_sync(FULL, s, 4, 16);
            s += __shfl_xor_sync(FULL, s, 8, 16);
            float yv = fmaf(c_l, s, du);
            if (ln == j) yk = yv;
        }
        g_yT[base + t0 + ln] = yk;
        dt_l = dt2; gl = g2; c_l = c2; du = du2;
    }
    float x = (Cb != 0.f) ? (z / Cb) : 0.f;
    carry[(size_t)g * N_SZ + ln] = x;
}

// ================= launch =================
extern "C" void kernel_launch(void* const* d_in, const int* in_sizes, int n_in,
                              void* d_out, int out_size) {
    const float* u     = (const float*)d_in[0];
    const float* Wdt   = (const float*)d_in[1];
    const float* bdt   = (const float*)d_in[2];
    const float* Wb    = (const float*)d_in[3];
    const float* bb    = (const float*)d_in[4];
    const float* Wc    = (const float*)d_in[5];
    const float* bc    = (const float*)d_in[6];
    const float* a_raw = (const float*)d_in[7];
    const float* Bbase = (const float*)d_in[8];
    const float* Cbase = (const float*)d_in[9];
    const float* Dp    = (const float*)d_in[10];

    float* out   = (float*)d_out;
    float* carry = out;                                  // (B, d, N) first
    float* y     = out + (size_t)B_SZ * D_SZ * N_SZ;     // then (B, L, d)

    cudaFuncSetAttribute(gemm_proj_kernel, cudaFuncAttributeMaxDynamicSharedMemorySize,
                         SMEM_TOT);

    conv_u_kernel<<<dim3(D_SZ / 32, TOK / 32), dim3(32, 32)>>>(u);
    conv_w_kernel<<<dim3(D_SZ / 32, D_SZ / 32), dim3(32, 32)>>>(Wdt, 0);
    conv_w_kernel<<<dim3(D_SZ / 32, D_SZ / 32), dim3(32, 32)>>>(Wb, D_SZ);
    conv_w_kernel<<<dim3(D_SZ / 32, D_SZ / 32), dim3(32, 32)>>>(Wc, 2 * D_SZ);
    gemm_proj_kernel<<<dim3(TOK / BM, ECOLS / BN), 256, SMEM_TOT>>>(bdt, bb, bc);
    scan_kernel<<<(B_SZ * D_SZ) / 16, 256>>>(a_raw, Bbase, Cbase, Dp, carry);
    transpose_y_kernel<<<dim3(L_SZ / 32, (B_SZ * D_SZ) / 32), dim3(32, 32)>>>(y);
}